// round 9
// baseline (speedup 1.0000x reference)
#include <cuda_runtime.h>

#define NN 50000
#define NE 1600000
#define HH 64
#define NG 16
#define DOUT 2

#define VPAD 68   // svec row stride (floats): conflict-free LDS.128

// Scratch (device globals; zero-initialized at load; consumers tail-zero)
__device__ __align__(16) float g_relu_sum[NN * HH];  // Σ relu(h1) per dest node
__device__ float g_deg[NN];                          // in-degree (float)
__device__ __align__(16) float g_pooled[NG * HH];

// ---------------------------------------------------------------------------
// Edge scatter kernel: warp processes 32 edges. Stage phase: coalesced edge
// loads + random x gathers + 1 deg RED per edge. Compute phase: per edge k,
// lanes compute features l and l+32 and issue 2 coalesced RED.32 into the
// destination node's row. Scalar float atomics only.
__global__ void __launch_bounds__(256) edge_kernel(
    const float* __restrict__ x,
    const int* __restrict__ ei,
    const float* __restrict__ ea,
    const float* __restrict__ ew1,   // [5,64]
    const float* __restrict__ eb1)   // [64]
{
    __shared__ __align__(16) float4 st4[8][32];   // (xr, a0, a1, a2)
    __shared__ float stx[8][32];                  // xc
    __shared__ int   stc[8][32];                  // dest node

    int warp = threadIdx.x >> 5, lane = threadIdx.x & 31;
    int base = (blockIdx.x * 8 + warp) * 32;      // NE % 256 == 0 -> always full
    int e = base + lane;

    // Per-lane weight columns for features lane and lane+32
    int ja = lane, jb = lane + 32;
    float w0a = __ldg(&ew1[0 * 64 + ja]), w1a = __ldg(&ew1[1 * 64 + ja]);
    float w2a = __ldg(&ew1[2 * 64 + ja]), w3a = __ldg(&ew1[3 * 64 + ja]);
    float w4a = __ldg(&ew1[4 * 64 + ja]), ba  = __ldg(&eb1[ja]);
    float w0b = __ldg(&ew1[0 * 64 + jb]), w1b = __ldg(&ew1[1 * 64 + jb]);
    float w2b = __ldg(&ew1[2 * 64 + jb]), w3b = __ldg(&ew1[3 * 64 + jb]);
    float w4b = __ldg(&ew1[4 * 64 + jb]), bb  = __ldg(&eb1[jb]);

    // Stage this warp's 32 edges
    int r = __ldg(&ei[e]);
    int c = __ldg(&ei[NE + e]);
    float xr = __ldg(&x[r]);
    float xc = __ldg(&x[c]);
    float a0 = __ldg(&ea[3 * e + 0]);
    float a1 = __ldg(&ea[3 * e + 1]);
    float a2 = __ldg(&ea[3 * e + 2]);
    atomicAdd(&g_deg[c], 1.0f);                   // scalar RED, no return

    st4[warp][lane] = make_float4(xr, a0, a1, a2);
    stx[warp][lane] = xc;
    stc[warp][lane] = c;
    __syncwarp();

#pragma unroll 8
    for (int k = 0; k < 32; k++) {
        float4 s  = st4[warp][k];                 // broadcast LDS.128
        float xck = stx[warp][k];
        int   ck  = stc[warp][k];
        float h0 = fmaf(s.x, w0a, fmaf(xck, w1a,
                   fmaf(s.y, w2a, fmaf(s.z, w3a, fmaf(s.w, w4a, ba)))));
        float h1 = fmaf(s.x, w0b, fmaf(xck, w1b,
                   fmaf(s.y, w2b, fmaf(s.z, w3b, fmaf(s.w, w4b, bb)))));
        float* dst = &g_relu_sum[(size_t)ck * HH];
        atomicAdd(dst + ja, fmaxf(h0, 0.f));      // coalesced RED.32 x2
        atomicAdd(dst + jb, fmaxf(h1, 0.f));
    }
}

// ---------------------------------------------------------------------------
__device__ __forceinline__ void fma4x4(float4& a, float4 iv, const float* wr) {
    float4 w0 = *(const float4*)(wr);
    float4 w1 = *(const float4*)(wr + 64);
    float4 w2 = *(const float4*)(wr + 128);
    float4 w3 = *(const float4*)(wr + 192);
    a.x = fmaf(iv.x, w0.x, a.x); a.y = fmaf(iv.x, w0.y, a.y);
    a.z = fmaf(iv.x, w0.z, a.z); a.w = fmaf(iv.x, w0.w, a.w);
    a.x = fmaf(iv.y, w1.x, a.x); a.y = fmaf(iv.y, w1.y, a.y);
    a.z = fmaf(iv.y, w1.z, a.z); a.w = fmaf(iv.y, w1.w, a.w);
    a.x = fmaf(iv.z, w2.x, a.x); a.y = fmaf(iv.z, w2.y, a.y);
    a.z = fmaf(iv.z, w2.z, a.z); a.w = fmaf(iv.z, w2.w, a.w);
    a.x = fmaf(iv.w, w3.x, a.x); a.y = fmaf(iv.w, w3.y, a.y);
    a.z = fmaf(iv.w, w3.z, a.z); a.w = fmaf(iv.w, w3.w, a.w);
}

// ---------------------------------------------------------------------------
// Fused node pipeline (spill-free via padded smem vector rows).
// Tail-zeroes g_relu_sum and g_deg after their final read.
__global__ void __launch_bounds__(128) node_fused_kernel(
    const float* __restrict__ x,
    const int* __restrict__ batch,
    const float* __restrict__ ew2, const float* __restrict__ eb2,
    const float* __restrict__ nw1, const float* __restrict__ nb1,
    const float* __restrict__ nw2, const float* __restrict__ nb2)
{
    extern __shared__ __align__(16) float sm[];
    float* sw    = sm;                        // 4160 floats
    float* svec  = sm + 4160;                 // 128*VPAD
    float* sb    = sm + 4160 + 128 * VPAD;    // 64
    float* spool = sb + 64;                   // 1024

    int tid = threadIdx.x;
    int base = blockIdx.x * 128;
    int n = base + tid;
    bool act = (n < NN);
    int nblk = min(128, NN - base);

    for (int i = tid; i < NG * HH; i += 128) spool[i] = 0.f;

    float4* gin = (float4*)g_relu_sum + (size_t)base * 16;
    const float4 z4 = make_float4(0.f, 0.f, 0.f, 0.f);
    for (int i = tid; i < nblk * 16; i += 128) {
        int nn = i >> 4, kv = i & 15;
        *(float4*)&svec[nn * VPAD + kv * 4] = gin[i];
        gin[i] = z4;                          // tail-zero for next replay
    }
    for (int i = tid; i < 1024; i += 128) ((float4*)sw)[i] = ((const float4*)ew2)[i];
    if (tid < 64) sb[tid] = eb2[tid];
    __syncthreads();

    float dg = 0.f, xn = 0.f;
    int g = 0;
    if (act) {
        dg = g_deg[n];
        g_deg[n] = 0.f;                       // tail-zero
        xn = __ldg(&x[n]);
        g  = batch[n];
    }

    float4 acc[16];
    float* myrow = &svec[tid * VPAD];

    // Phase A: agg = deg*eb2 + relu_sum @ ew2
    if (act) {
#pragma unroll
        for (int jv = 0; jv < 16; jv++)
            acc[jv] = make_float4(dg * sb[jv*4], dg * sb[jv*4+1],
                                  dg * sb[jv*4+2], dg * sb[jv*4+3]);
        for (int kv = 0; kv < 16; kv++) {
            float4 iv = *(const float4*)&myrow[kv * 4];
#pragma unroll
            for (int jv = 0; jv < 16; jv++)
                fma4x4(acc[jv], iv, &sw[kv * 4 * 64 + jv * 4]);
        }
#pragma unroll
        for (int jv = 0; jv < 16; jv++)
            *(float4*)&myrow[jv * 4] = acc[jv];
    }
    __syncthreads();

    for (int i = tid; i < 1040; i += 128) ((float4*)sw)[i] = ((const float4*)nw1)[i];
    if (tid < 64) sb[tid] = nb1[tid];
    __syncthreads();

    // Phase B: t = relu(nb1 + x*nw1[0] + agg @ nw1[1:])
    if (act) {
#pragma unroll
        for (int jv = 0; jv < 16; jv++)
            acc[jv] = make_float4(fmaf(xn, sw[jv*4+0], sb[jv*4+0]),
                                  fmaf(xn, sw[jv*4+1], sb[jv*4+1]),
                                  fmaf(xn, sw[jv*4+2], sb[jv*4+2]),
                                  fmaf(xn, sw[jv*4+3], sb[jv*4+3]));
        for (int kv = 0; kv < 16; kv++) {
            float4 iv = *(const float4*)&myrow[kv * 4];
#pragma unroll
            for (int jv = 0; jv < 16; jv++)
                fma4x4(acc[jv], iv, &sw[(kv * 4 + 1) * 64 + jv * 4]);
        }
#pragma unroll
        for (int jv = 0; jv < 16; jv++) {
            acc[jv].x = fmaxf(acc[jv].x, 0.f); acc[jv].y = fmaxf(acc[jv].y, 0.f);
            acc[jv].z = fmaxf(acc[jv].z, 0.f); acc[jv].w = fmaxf(acc[jv].w, 0.f);
            *(float4*)&myrow[jv * 4] = acc[jv];
        }
    }
    __syncthreads();

    for (int i = tid; i < 1024; i += 128) ((float4*)sw)[i] = ((const float4*)nw2)[i];
    if (tid < 64) sb[tid] = nb2[tid];
    __syncthreads();

    // Phase C: h = nb2 + t @ nw2; pool
    if (act) {
#pragma unroll
        for (int jv = 0; jv < 16; jv++)
            acc[jv] = make_float4(sb[jv*4], sb[jv*4+1], sb[jv*4+2], sb[jv*4+3]);
        for (int kv = 0; kv < 16; kv++) {
            float4 iv = *(const float4*)&myrow[kv * 4];
#pragma unroll
            for (int jv = 0; jv < 16; jv++)
                fma4x4(acc[jv], iv, &sw[kv * 4 * 64 + jv * 4]);
        }
#pragma unroll
        for (int jv = 0; jv < 16; jv++) {
            atomicAdd(&spool[g * HH + jv * 4 + 0], acc[jv].x);
            atomicAdd(&spool[g * HH + jv * 4 + 1], acc[jv].y);
            atomicAdd(&spool[g * HH + jv * 4 + 2], acc[jv].z);
            atomicAdd(&spool[g * HH + jv * 4 + 3], acc[jv].w);
        }
    }
    __syncthreads();
    for (int i = tid; i < NG * HH; i += 128)
        atomicAdd(&g_pooled[i], spool[i]);
}

// ---------------------------------------------------------------------------
// Head MLP; tail-zeroes g_pooled after reading (last consumer).
__global__ void __launch_bounds__(1024) out_kernel(
    const float* __restrict__ ow1, const float* __restrict__ ob1,
    const float* __restrict__ ow2, const float* __restrict__ ob2,
    const float* __restrict__ ow3, const float* __restrict__ ob3,
    const float* __restrict__ ow4, const float* __restrict__ ob4,
    float* __restrict__ out)
{
    __shared__ float sa[NG * HH];
    __shared__ float sbuf[NG * HH];
    int tid = threadIdx.x;
    sa[tid] = g_pooled[tid];
    g_pooled[tid] = 0.f;               // tail-zero for next replay
    __syncthreads();

    int g = tid >> 6, j = tid & 63;

    float v = __ldg(&ob1[j]);
#pragma unroll 16
    for (int k = 0; k < 64; k++) v = fmaf(sa[g * 64 + k], __ldg(&ow1[k * 64 + j]), v);
    sbuf[tid] = fmaxf(v, 0.f);
    __syncthreads();

    v = __ldg(&ob2[j]);
#pragma unroll 16
    for (int k = 0; k < 64; k++) v = fmaf(sbuf[g * 64 + k], __ldg(&ow2[k * 64 + j]), v);
    sa[tid] = fmaxf(v, 0.f);
    __syncthreads();

    v = __ldg(&ob3[j]);
#pragma unroll 16
    for (int k = 0; k < 64; k++) v = fmaf(sa[g * 64 + k], __ldg(&ow3[k * 64 + j]), v);
    sbuf[tid] = fmaxf(v, 0.f);
    __syncthreads();

    if (j < DOUT) {
        float o = __ldg(&ob4[j]);
#pragma unroll 16
        for (int k = 0; k < 64; k++)
            o = fmaf(sbuf[g * 64 + k], __ldg(&ow4[k * DOUT + j]), o);
        out[g * DOUT + j] = o;
    }
}

// ---------------------------------------------------------------------------
extern "C" void kernel_launch(void* const* d_in, const int* in_sizes, int n_in,
                              void* d_out, int out_size) {
    const float* x     = (const float*)d_in[0];
    const int* ei      = (const int*)d_in[1];
    const float* ea    = (const float*)d_in[2];
    const int* batch   = (const int*)d_in[3];
    const float* ew1 = (const float*)d_in[4];
    const float* eb1 = (const float*)d_in[5];
    const float* ew2 = (const float*)d_in[6];
    const float* eb2 = (const float*)d_in[7];
    const float* nw1 = (const float*)d_in[8];
    const float* nb1 = (const float*)d_in[9];
    const float* nw2 = (const float*)d_in[10];
    const float* nb2 = (const float*)d_in[11];
    const float* ow1 = (const float*)d_in[12];
    const float* ob1 = (const float*)d_in[13];
    const float* ow2 = (const float*)d_in[14];
    const float* ob2 = (const float*)d_in[15];
    const float* ow3 = (const float*)d_in[16];
    const float* ob3 = (const float*)d_in[17];
    const float* ow4 = (const float*)d_in[18];
    const float* ob4 = (const float*)d_in[19];
    float* out = (float*)d_out;

    const int node_smem = (4160 + 128 * VPAD + 64 + 1024) * 4;   // 55808 B
    static int smem_set = 0;
    if (!smem_set) {
        cudaFuncSetAttribute(node_fused_kernel,
                             cudaFuncAttributeMaxDynamicSharedMemorySize, node_smem);
        smem_set = 1;
    }

    edge_kernel<<<NE / 256, 256>>>(x, ei, ea, ew1, eb1);         // 1
    node_fused_kernel<<<(NN + 127) / 128, 128, node_smem>>>(x, batch,
        ew2, eb2, nw1, nb1, nw2, nb2);                           // 2
    out_kernel<<<1, NG * HH>>>(ow1, ob1, ow2, ob2, ow3, ob3, ow4, ob4, out); // 3
}

// round 10
// speedup vs baseline: 1.1882x; 1.1882x over previous
#include <cuda_runtime.h>

#define NN 50000
#define NE 1600000
#define HH 64
#define NG 16
#define DOUT 2

#define VPAD 68   // svec row stride (floats): conflict-free LDS.128

// Scratch (device globals; zero-initialized at load; consumers tail-zero)
__device__ __align__(16) float g_relu_sum[NN * HH];  // Σ relu(h1) per dest node
__device__ float g_deg[NN];                          // in-degree (float)
__device__ __align__(16) float g_pooled[NG * HH];
__device__ int g_done;                               // last-block counter

// ---------------------------------------------------------------------------
// Edge scatter: warp processes 32 edges; coalesced RED.32 x2 per edge.
__global__ void __launch_bounds__(256) edge_kernel(
    const float* __restrict__ x,
    const int* __restrict__ ei,
    const float* __restrict__ ea,
    const float* __restrict__ ew1,   // [5,64]
    const float* __restrict__ eb1)   // [64]
{
    __shared__ __align__(16) float4 st4[8][32];   // (xr, a0, a1, a2)
    __shared__ float stx[8][32];                  // xc
    __shared__ int   stc[8][32];                  // dest node

    int warp = threadIdx.x >> 5, lane = threadIdx.x & 31;
    int base = (blockIdx.x * 8 + warp) * 32;      // NE % 256 == 0
    int e = base + lane;

    int ja = lane, jb = lane + 32;
    float w0a = __ldg(&ew1[0 * 64 + ja]), w1a = __ldg(&ew1[1 * 64 + ja]);
    float w2a = __ldg(&ew1[2 * 64 + ja]), w3a = __ldg(&ew1[3 * 64 + ja]);
    float w4a = __ldg(&ew1[4 * 64 + ja]), ba  = __ldg(&eb1[ja]);
    float w0b = __ldg(&ew1[0 * 64 + jb]), w1b = __ldg(&ew1[1 * 64 + jb]);
    float w2b = __ldg(&ew1[2 * 64 + jb]), w3b = __ldg(&ew1[3 * 64 + jb]);
    float w4b = __ldg(&ew1[4 * 64 + jb]), bb  = __ldg(&eb1[jb]);

    int r = __ldg(&ei[e]);
    int c = __ldg(&ei[NE + e]);
    float xr = __ldg(&x[r]);
    float xc = __ldg(&x[c]);
    float a0 = __ldg(&ea[3 * e + 0]);
    float a1 = __ldg(&ea[3 * e + 1]);
    float a2 = __ldg(&ea[3 * e + 2]);
    atomicAdd(&g_deg[c], 1.0f);

    st4[warp][lane] = make_float4(xr, a0, a1, a2);
    stx[warp][lane] = xc;
    stc[warp][lane] = c;
    __syncwarp();

#pragma unroll 8
    for (int k = 0; k < 32; k++) {
        float4 s  = st4[warp][k];
        float xck = stx[warp][k];
        int   ck  = stc[warp][k];
        float h0 = fmaf(s.x, w0a, fmaf(xck, w1a,
                   fmaf(s.y, w2a, fmaf(s.z, w3a, fmaf(s.w, w4a, ba)))));
        float h1 = fmaf(s.x, w0b, fmaf(xck, w1b,
                   fmaf(s.y, w2b, fmaf(s.z, w3b, fmaf(s.w, w4b, bb)))));
        float* dst = &g_relu_sum[(size_t)ck * HH];
        atomicAdd(dst + ja, fmaxf(h0, 0.f));
        atomicAdd(dst + jb, fmaxf(h1, 0.f));
    }
}

// ---------------------------------------------------------------------------
__device__ __forceinline__ void fma4x4(float4& a, float4 iv, const float* wr) {
    float4 w0 = *(const float4*)(wr);
    float4 w1 = *(const float4*)(wr + 64);
    float4 w2 = *(const float4*)(wr + 128);
    float4 w3 = *(const float4*)(wr + 192);
    a.x = fmaf(iv.x, w0.x, a.x); a.y = fmaf(iv.x, w0.y, a.y);
    a.z = fmaf(iv.x, w0.z, a.z); a.w = fmaf(iv.x, w0.w, a.w);
    a.x = fmaf(iv.y, w1.x, a.x); a.y = fmaf(iv.y, w1.y, a.y);
    a.z = fmaf(iv.y, w1.z, a.z); a.w = fmaf(iv.y, w1.w, a.w);
    a.x = fmaf(iv.z, w2.x, a.x); a.y = fmaf(iv.z, w2.y, a.y);
    a.z = fmaf(iv.z, w2.z, a.z); a.w = fmaf(iv.z, w2.w, a.w);
    a.x = fmaf(iv.w, w3.x, a.x); a.y = fmaf(iv.w, w3.y, a.y);
    a.z = fmaf(iv.w, w3.z, a.z); a.w = fmaf(iv.w, w3.w, a.w);
}

// ---------------------------------------------------------------------------
// Fused node pipeline + head MLP (last block). 256 threads, 128 nodes/block:
// thread pair (2k, 2k+1) shares node k, each owns 8 of 16 jv tiles.
#define NODES_B 128
__global__ void __launch_bounds__(256) node_out_kernel(
    const float* __restrict__ x,
    const int* __restrict__ batch,
    const float* __restrict__ ew2, const float* __restrict__ eb2,
    const float* __restrict__ nw1, const float* __restrict__ nb1,
    const float* __restrict__ nw2, const float* __restrict__ nb2,
    const float* __restrict__ ow1, const float* __restrict__ ob1,
    const float* __restrict__ ow2, const float* __restrict__ ob2,
    const float* __restrict__ ow3, const float* __restrict__ ob3,
    const float* __restrict__ ow4, const float* __restrict__ ob4,
    float* __restrict__ out)
{
    extern __shared__ __align__(16) float sm[];
    float* sw    = sm;                          // 4160 floats
    float* svec  = sm + 4160;                   // NODES_B * VPAD
    float* sb    = sm + 4160 + NODES_B * VPAD;  // 64
    float* spool = sb + 64;                     // 1024

    int tid = threadIdx.x;
    int nid = tid >> 1;           // local node 0..127
    int hf  = tid & 1;            // jv half
    int base = blockIdx.x * NODES_B;
    int n = base + nid;
    bool act = (n < NN);
    int nblk = min(NODES_B, NN - base);

    for (int i = tid; i < NG * HH; i += 256) spool[i] = 0.f;

    float4* gin = (float4*)g_relu_sum + (size_t)base * 16;
    const float4 z4 = make_float4(0.f, 0.f, 0.f, 0.f);
    for (int i = tid; i < nblk * 16; i += 256) {
        int nn = i >> 4, kv = i & 15;
        *(float4*)&svec[nn * VPAD + kv * 4] = gin[i];
        gin[i] = z4;                            // tail-zero
    }
    for (int i = tid; i < 1024; i += 256) ((float4*)sw)[i] = ((const float4*)ew2)[i];
    if (tid < 64) sb[tid] = eb2[tid];
    __syncthreads();

    float dg = 0.f, xn = 0.f;
    int g = 0;
    if (act) {
        dg = g_deg[n];
        if (hf == 0) g_deg[n] = 0.f;            // tail-zero once
        xn = __ldg(&x[n]);
        g  = batch[n];
    }

    float4 acc[8];
    float* myrow = &svec[nid * VPAD];
    int jv0 = hf * 8;                           // this thread's jv range

    // Phase A: agg = deg*eb2 + relu_sum @ ew2
    if (act) {
#pragma unroll
        for (int q = 0; q < 8; q++) {
            int jv = jv0 + q;
            acc[q] = make_float4(dg * sb[jv*4], dg * sb[jv*4+1],
                                 dg * sb[jv*4+2], dg * sb[jv*4+3]);
        }
        for (int kv = 0; kv < 16; kv++) {
            float4 iv = *(const float4*)&myrow[kv * 4];
#pragma unroll
            for (int q = 0; q < 8; q++)
                fma4x4(acc[q], iv, &sw[kv * 4 * 64 + (jv0 + q) * 4]);
        }
        __syncwarp();                           // pair write/read separation
#pragma unroll
        for (int q = 0; q < 8; q++)
            *(float4*)&myrow[(jv0 + q) * 4] = acc[q];
    }
    __syncthreads();

    for (int i = tid; i < 1040; i += 256) ((float4*)sw)[i] = ((const float4*)nw1)[i];
    if (tid < 64) sb[tid] = nb1[tid];
    __syncthreads();

    // Phase B: t = relu(nb1 + x*nw1[0] + agg @ nw1[1:])
    if (act) {
#pragma unroll
        for (int q = 0; q < 8; q++) {
            int jv = jv0 + q;
            acc[q] = make_float4(fmaf(xn, sw[jv*4+0], sb[jv*4+0]),
                                 fmaf(xn, sw[jv*4+1], sb[jv*4+1]),
                                 fmaf(xn, sw[jv*4+2], sb[jv*4+2]),
                                 fmaf(xn, sw[jv*4+3], sb[jv*4+3]));
        }
        for (int kv = 0; kv < 16; kv++) {
            float4 iv = *(const float4*)&myrow[kv * 4];
#pragma unroll
            for (int q = 0; q < 8; q++)
                fma4x4(acc[q], iv, &sw[(kv * 4 + 1) * 64 + (jv0 + q) * 4]);
        }
        __syncwarp();
#pragma unroll
        for (int q = 0; q < 8; q++) {
            acc[q].x = fmaxf(acc[q].x, 0.f); acc[q].y = fmaxf(acc[q].y, 0.f);
            acc[q].z = fmaxf(acc[q].z, 0.f); acc[q].w = fmaxf(acc[q].w, 0.f);
            *(float4*)&myrow[(jv0 + q) * 4] = acc[q];
        }
    }
    __syncthreads();

    for (int i = tid; i < 1024; i += 256) ((float4*)sw)[i] = ((const float4*)nw2)[i];
    if (tid < 64) sb[tid] = nb2[tid];
    __syncthreads();

    // Phase C: h = nb2 + t @ nw2; pool
    if (act) {
#pragma unroll
        for (int q = 0; q < 8; q++) {
            int jv = jv0 + q;
            acc[q] = make_float4(sb[jv*4], sb[jv*4+1], sb[jv*4+2], sb[jv*4+3]);
        }
        for (int kv = 0; kv < 16; kv++) {
            float4 iv = *(const float4*)&myrow[kv * 4];
#pragma unroll
            for (int q = 0; q < 8; q++)
                fma4x4(acc[q], iv, &sw[kv * 4 * 64 + (jv0 + q) * 4]);
        }
#pragma unroll
        for (int q = 0; q < 8; q++) {
            int jv = jv0 + q;
            atomicAdd(&spool[g * HH + jv * 4 + 0], acc[q].x);
            atomicAdd(&spool[g * HH + jv * 4 + 1], acc[q].y);
            atomicAdd(&spool[g * HH + jv * 4 + 2], acc[q].z);
            atomicAdd(&spool[g * HH + jv * 4 + 3], acc[q].w);
        }
    }
    __syncthreads();
    for (int i = tid; i < NG * HH; i += 256)
        atomicAdd(&g_pooled[i], spool[i]);

    // ---- last-block: head MLP ----
    __shared__ int s_last;
    __syncthreads();
    if (tid == 0) {
        __threadfence();
        int done = atomicAdd(&g_done, 1);
        s_last = (done == (int)gridDim.x - 1) ? 1 : 0;
    }
    __syncthreads();
    if (!s_last) return;
    __threadfence();

    float* sa   = spool;          // reuse
    float* sbuf = svec;           // reuse (plenty)
    for (int i = tid; i < NG * HH; i += 256) {
        sa[i] = __ldcg(&g_pooled[i]);   // L2 read, bypass L1
        g_pooled[i] = 0.f;              // tail-zero
    }
    if (tid == 0) g_done = 0;           // reset counter
    __syncthreads();

    // 1024 items, 256 threads -> 4 items each
#pragma unroll
    for (int it = 0; it < 4; it++) {
        int item = tid + it * 256;
        int gg = item >> 6, j = item & 63;
        float v = __ldg(&ob1[j]);
#pragma unroll 16
        for (int k = 0; k < 64; k++) v = fmaf(sa[gg * 64 + k], __ldg(&ow1[k * 64 + j]), v);
        sbuf[item] = fmaxf(v, 0.f);
    }
    __syncthreads();
#pragma unroll
    for (int it = 0; it < 4; it++) {
        int item = tid + it * 256;
        int gg = item >> 6, j = item & 63;
        float v = __ldg(&ob2[j]);
#pragma unroll 16
        for (int k = 0; k < 64; k++) v = fmaf(sbuf[gg * 64 + k], __ldg(&ow2[k * 64 + j]), v);
        sa[item] = fmaxf(v, 0.f);
    }
    __syncthreads();
#pragma unroll
    for (int it = 0; it < 4; it++) {
        int item = tid + it * 256;
        int gg = item >> 6, j = item & 63;
        float v = __ldg(&ob3[j]);
#pragma unroll 16
        for (int k = 0; k < 64; k++) v = fmaf(sa[gg * 64 + k], __ldg(&ow3[k * 64 + j]), v);
        sbuf[item] = fmaxf(v, 0.f);
    }
    __syncthreads();
    if (tid < NG * DOUT) {
        int gg = tid / DOUT, j = tid % DOUT;
        float o = __ldg(&ob4[j]);
#pragma unroll 16
        for (int k = 0; k < 64; k++)
            o = fmaf(sbuf[gg * 64 + k], __ldg(&ow4[k * DOUT + j]), o);
        out[gg * DOUT + j] = o;
    }
}

// ---------------------------------------------------------------------------
extern "C" void kernel_launch(void* const* d_in, const int* in_sizes, int n_in,
                              void* d_out, int out_size) {
    const float* x     = (const float*)d_in[0];
    const int* ei      = (const int*)d_in[1];
    const float* ea    = (const float*)d_in[2];
    const int* batch   = (const int*)d_in[3];
    const float* ew1 = (const float*)d_in[4];
    const float* eb1 = (const float*)d_in[5];
    const float* ew2 = (const float*)d_in[6];
    const float* eb2 = (const float*)d_in[7];
    const float* nw1 = (const float*)d_in[8];
    const float* nb1 = (const float*)d_in[9];
    const float* nw2 = (const float*)d_in[10];
    const float* nb2 = (const float*)d_in[11];
    const float* ow1 = (const float*)d_in[12];
    const float* ob1 = (const float*)d_in[13];
    const float* ow2 = (const float*)d_in[14];
    const float* ob2 = (const float*)d_in[15];
    const float* ow3 = (const float*)d_in[16];
    const float* ob3 = (const float*)d_in[17];
    const float* ow4 = (const float*)d_in[18];
    const float* ob4 = (const float*)d_in[19];
    float* out = (float*)d_out;

    const int node_smem = (4160 + NODES_B * VPAD + 64 + 1024) * 4;   // 55808 B
    static int smem_set = 0;
    if (!smem_set) {
        cudaFuncSetAttribute(node_out_kernel,
                             cudaFuncAttributeMaxDynamicSharedMemorySize, node_smem);
        smem_set = 1;
    }

    edge_kernel<<<NE / 256, 256>>>(x, ei, ea, ew1, eb1);               // 1
    node_out_kernel<<<(NN + NODES_B - 1) / NODES_B, 256, node_smem>>>( // 2 (slot 4 = ncu)
        x, batch, ew2, eb2, nw1, nb1, nw2, nb2,
        ow1, ob1, ow2, ob2, ow3, ob3, ow4, ob4, out);
}

// round 11
// speedup vs baseline: 1.4162x; 1.1919x over previous
#include <cuda_runtime.h>

#define NN 50000
#define NE 1600000
#define HH 64
#define NG 16
#define DOUT 2

#define VPAD 68     // svec row stride (floats); 8 rows @ stride-8 hit banks {0,4..28}
#define NODES_B 256 // nodes per block

// Scratch (device globals; zero-initialized at load; consumers tail-zero)
__device__ __align__(16) float g_relu_sum[NN * HH];
__device__ float g_deg[NN];
__device__ __align__(16) float g_pooled[NG * HH];
__device__ int g_done;

// ---------------------------------------------------------------------------
// Edge scatter: warp processes 32 edges; coalesced RED.32 x2 per edge.
__global__ void __launch_bounds__(256) edge_kernel(
    const float* __restrict__ x,
    const int* __restrict__ ei,
    const float* __restrict__ ea,
    const float* __restrict__ ew1,   // [5,64]
    const float* __restrict__ eb1)   // [64]
{
    __shared__ __align__(16) float4 st4[8][32];
    __shared__ float stx[8][32];
    __shared__ int   stc[8][32];

    int warp = threadIdx.x >> 5, lane = threadIdx.x & 31;
    int e = (blockIdx.x * 8 + warp) * 32 + lane;   // NE % 256 == 0

    int ja = lane, jb = lane + 32;
    float w0a = __ldg(&ew1[0 * 64 + ja]), w1a = __ldg(&ew1[1 * 64 + ja]);
    float w2a = __ldg(&ew1[2 * 64 + ja]), w3a = __ldg(&ew1[3 * 64 + ja]);
    float w4a = __ldg(&ew1[4 * 64 + ja]), ba  = __ldg(&eb1[ja]);
    float w0b = __ldg(&ew1[0 * 64 + jb]), w1b = __ldg(&ew1[1 * 64 + jb]);
    float w2b = __ldg(&ew1[2 * 64 + jb]), w3b = __ldg(&ew1[3 * 64 + jb]);
    float w4b = __ldg(&ew1[4 * 64 + jb]), bb  = __ldg(&eb1[jb]);

    int r = __ldg(&ei[e]);
    int c = __ldg(&ei[NE + e]);
    float xr = __ldg(&x[r]);
    float xc = __ldg(&x[c]);
    float a0 = __ldg(&ea[3 * e + 0]);
    float a1 = __ldg(&ea[3 * e + 1]);
    float a2 = __ldg(&ea[3 * e + 2]);
    atomicAdd(&g_deg[c], 1.0f);

    st4[warp][lane] = make_float4(xr, a0, a1, a2);
    stx[warp][lane] = xc;
    stc[warp][lane] = c;
    __syncwarp();

#pragma unroll 8
    for (int k = 0; k < 32; k++) {
        float4 s  = st4[warp][k];
        float xck = stx[warp][k];
        int   ck  = stc[warp][k];
        float h0 = fmaf(s.x, w0a, fmaf(xck, w1a,
                   fmaf(s.y, w2a, fmaf(s.z, w3a, fmaf(s.w, w4a, ba)))));
        float h1 = fmaf(s.x, w0b, fmaf(xck, w1b,
                   fmaf(s.y, w2b, fmaf(s.z, w3b, fmaf(s.w, w4b, bb)))));
        float* dst = &g_relu_sum[(size_t)ck * HH];
        atomicAdd(dst + ja, fmaxf(h0, 0.f));
        atomicAdd(dst + jb, fmaxf(h1, 0.f));
    }
}

// ---------------------------------------------------------------------------
// 16-FFMA micro-tile with preloaded weight rows.
__device__ __forceinline__ void fma16(float4& a, float4 iv,
                                      float4 w0, float4 w1, float4 w2, float4 w3) {
    a.x = fmaf(iv.x, w0.x, a.x); a.y = fmaf(iv.x, w0.y, a.y);
    a.z = fmaf(iv.x, w0.z, a.z); a.w = fmaf(iv.x, w0.w, a.w);
    a.x = fmaf(iv.y, w1.x, a.x); a.y = fmaf(iv.y, w1.y, a.y);
    a.z = fmaf(iv.y, w1.z, a.z); a.w = fmaf(iv.y, w1.w, a.w);
    a.x = fmaf(iv.z, w2.x, a.x); a.y = fmaf(iv.z, w2.y, a.y);
    a.z = fmaf(iv.z, w2.z, a.z); a.w = fmaf(iv.z, w2.w, a.w);
    a.x = fmaf(iv.w, w3.x, a.x); a.y = fmaf(iv.w, w3.y, a.y);
    a.z = fmaf(iv.w, w3.z, a.z); a.w = fmaf(iv.w, w3.w, a.w);
}

// ---------------------------------------------------------------------------
// Fused node pipeline + head MLP (last block).
// 256 threads = 8 warps; warp covers 32 nodes (8 slots x 4 m); 4 q-threads/node.
// Thread: M=4 nodes (stride 8 in warp), J=4 jv tiles (contiguous, offset q*16).
// Each weight LDS feeds 4 nodes -> 3.2x less crossbar traffic than R10.
__global__ void __launch_bounds__(256, 2) node_out_kernel(
    const float* __restrict__ x,
    const int* __restrict__ batch,
    const float* __restrict__ ew2, const float* __restrict__ eb2,
    const float* __restrict__ nw1, const float* __restrict__ nb1,
    const float* __restrict__ nw2, const float* __restrict__ nb2,
    const float* __restrict__ ow1, const float* __restrict__ ob1,
    const float* __restrict__ ow2, const float* __restrict__ ob2,
    const float* __restrict__ ow3, const float* __restrict__ ob3,
    const float* __restrict__ ow4, const float* __restrict__ ob4,
    float* __restrict__ out)
{
    extern __shared__ __align__(16) float sm[];
    float* sw    = sm;                          // 4160 floats (65x64 max)
    float* svec  = sm + 4160;                   // NODES_B * VPAD
    float* sb    = sm + 4160 + NODES_B * VPAD;  // 64
    float* spool = sb + 64;                     // 1024

    int tid  = threadIdx.x;
    int warp = tid >> 5, lane = tid & 31;
    int n8 = lane >> 2, q = lane & 3;
    int base = blockIdx.x * NODES_B;
    int wrow = warp * 32 + n8;                  // local row for m=0

    int lrow[4], node[4];
    bool act[4];
#pragma unroll
    for (int m = 0; m < 4; m++) {
        lrow[m] = wrow + m * 8;
        node[m] = base + lrow[m];
        act[m]  = (node[m] < NN);
    }
    int nblk = min(NODES_B, NN - base);

    for (int i = tid; i < NG * HH; i += 256) spool[i] = 0.f;

    // Coalesced load + tail-zero of relu_sum
    float4* gin = (float4*)g_relu_sum + (size_t)base * 16;
    const float4 z4 = make_float4(0.f, 0.f, 0.f, 0.f);
    for (int i = tid; i < nblk * 16; i += 256) {
        int nn = i >> 4, kv = i & 15;
        *(float4*)&svec[nn * VPAD + kv * 4] = gin[i];
        gin[i] = z4;
    }
    for (int i = tid; i < 1024; i += 256) ((float4*)sw)[i] = ((const float4*)ew2)[i];
    if (tid < 64) sb[tid] = eb2[tid];
    __syncthreads();

    float dg[4], xn[4];
    int g[4];
#pragma unroll
    for (int m = 0; m < 4; m++) {
        dg[m] = 0.f; xn[m] = 0.f; g[m] = 0;
        if (act[m]) {
            dg[m] = g_deg[node[m]];
            if (q == 0) g_deg[node[m]] = 0.f;   // tail-zero once
            xn[m] = __ldg(&x[node[m]]);
            g[m]  = batch[node[m]];
        }
    }

    float4 acc[4][4];                           // [m][qq]
    int jc = q * 16;                            // this thread's output col base (floats)

    // ================= Phase A: agg = deg*eb2 + relu_sum @ ew2 =================
#pragma unroll
    for (int m = 0; m < 4; m++)
#pragma unroll
        for (int qq = 0; qq < 4; qq++) {
            const float* b4 = &sb[jc + qq * 4];
            acc[m][qq] = make_float4(dg[m]*b4[0], dg[m]*b4[1], dg[m]*b4[2], dg[m]*b4[3]);
        }
    for (int kv = 0; kv < 16; kv++) {
        float4 iv[4];
#pragma unroll
        for (int m = 0; m < 4; m++) iv[m] = *(const float4*)&svec[lrow[m]*VPAD + kv*4];
#pragma unroll
        for (int qq = 0; qq < 4; qq++) {
            const float* wr = &sw[kv * 4 * 64 + jc + qq * 4];
            float4 w0 = *(const float4*)(wr);
            float4 w1 = *(const float4*)(wr + 64);
            float4 w2 = *(const float4*)(wr + 128);
            float4 w3 = *(const float4*)(wr + 192);
#pragma unroll
            for (int m = 0; m < 4; m++) fma16(acc[m][qq], iv[m], w0, w1, w2, w3);
        }
    }
    __syncwarp();
#pragma unroll
    for (int m = 0; m < 4; m++)
        if (act[m])
#pragma unroll
            for (int qq = 0; qq < 4; qq++)
                *(float4*)&svec[lrow[m]*VPAD + jc + qq*4] = acc[m][qq];
    __syncthreads();

    for (int i = tid; i < 1040; i += 256) ((float4*)sw)[i] = ((const float4*)nw1)[i];
    if (tid < 64) sb[tid] = nb1[tid];
    __syncthreads();

    // ============ Phase B: t = relu(nb1 + x*nw1[0] + agg @ nw1[1:]) ============
#pragma unroll
    for (int m = 0; m < 4; m++)
#pragma unroll
        for (int qq = 0; qq < 4; qq++) {
            const float* b4 = &sb[jc + qq * 4];
            const float* w0r = &sw[jc + qq * 4];   // nw1 row 0
            acc[m][qq] = make_float4(fmaf(xn[m], w0r[0], b4[0]),
                                     fmaf(xn[m], w0r[1], b4[1]),
                                     fmaf(xn[m], w0r[2], b4[2]),
                                     fmaf(xn[m], w0r[3], b4[3]));
        }
    for (int kv = 0; kv < 16; kv++) {
        float4 iv[4];
#pragma unroll
        for (int m = 0; m < 4; m++) iv[m] = *(const float4*)&svec[lrow[m]*VPAD + kv*4];
#pragma unroll
        for (int qq = 0; qq < 4; qq++) {
            const float* wr = &sw[(kv * 4 + 1) * 64 + jc + qq * 4];
            float4 w0 = *(const float4*)(wr);
            float4 w1 = *(const float4*)(wr + 64);
            float4 w2 = *(const float4*)(wr + 128);
            float4 w3 = *(const float4*)(wr + 192);
#pragma unroll
            for (int m = 0; m < 4; m++) fma16(acc[m][qq], iv[m], w0, w1, w2, w3);
        }
    }
    __syncwarp();
#pragma unroll
    for (int m = 0; m < 4; m++)
        if (act[m])
#pragma unroll
            for (int qq = 0; qq < 4; qq++) {
                float4 a = acc[m][qq];
                a.x = fmaxf(a.x, 0.f); a.y = fmaxf(a.y, 0.f);
                a.z = fmaxf(a.z, 0.f); a.w = fmaxf(a.w, 0.f);
                *(float4*)&svec[lrow[m]*VPAD + jc + qq*4] = a;
            }
    __syncthreads();

    for (int i = tid; i < 1024; i += 256) ((float4*)sw)[i] = ((const float4*)nw2)[i];
    if (tid < 64) sb[tid] = nb2[tid];
    __syncthreads();

    // ================= Phase C: h = nb2 + t @ nw2; pool =================
#pragma unroll
    for (int m = 0; m < 4; m++)
#pragma unroll
        for (int qq = 0; qq < 4; qq++) {
            const float* b4 = &sb[jc + qq * 4];
            acc[m][qq] = make_float4(b4[0], b4[1], b4[2], b4[3]);
        }
    for (int kv = 0; kv < 16; kv++) {
        float4 iv[4];
#pragma unroll
        for (int m = 0; m < 4; m++) iv[m] = *(const float4*)&svec[lrow[m]*VPAD + kv*4];
#pragma unroll
        for (int qq = 0; qq < 4; qq++) {
            const float* wr = &sw[kv * 4 * 64 + jc + qq * 4];
            float4 w0 = *(const float4*)(wr);
            float4 w1 = *(const float4*)(wr + 64);
            float4 w2 = *(const float4*)(wr + 128);
            float4 w3 = *(const float4*)(wr + 192);
#pragma unroll
            for (int m = 0; m < 4; m++) fma16(acc[m][qq], iv[m], w0, w1, w2, w3);
        }
    }
#pragma unroll
    for (int m = 0; m < 4; m++)
        if (act[m])
#pragma unroll
            for (int qq = 0; qq < 4; qq++) {
                float* dst = &spool[g[m] * HH + jc + qq * 4];
                atomicAdd(dst + 0, acc[m][qq].x);
                atomicAdd(dst + 1, acc[m][qq].y);
                atomicAdd(dst + 2, acc[m][qq].z);
                atomicAdd(dst + 3, acc[m][qq].w);
            }
    __syncthreads();
    for (int i = tid; i < NG * HH; i += 256)
        atomicAdd(&g_pooled[i], spool[i]);

    // ---- last-block: head MLP ----
    __shared__ int s_last;
    __syncthreads();
    if (tid == 0) {
        __threadfence();
        int done = atomicAdd(&g_done, 1);
        s_last = (done == (int)gridDim.x - 1) ? 1 : 0;
    }
    __syncthreads();
    if (!s_last) return;
    __threadfence();

    float* sa   = spool;
    float* sbuf = svec;
    for (int i = tid; i < NG * HH; i += 256) {
        sa[i] = __ldcg(&g_pooled[i]);
        g_pooled[i] = 0.f;
    }
    if (tid == 0) g_done = 0;
    __syncthreads();

#pragma unroll
    for (int it = 0; it < 4; it++) {
        int item = tid + it * 256;
        int gg = item >> 6, j = item & 63;
        float v = __ldg(&ob1[j]);
#pragma unroll 16
        for (int k = 0; k < 64; k++) v = fmaf(sa[gg * 64 + k], __ldg(&ow1[k * 64 + j]), v);
        sbuf[item] = fmaxf(v, 0.f);
    }
    __syncthreads();
#pragma unroll
    for (int it = 0; it < 4; it++) {
        int item = tid + it * 256;
        int gg = item >> 6, j = item & 63;
        float v = __ldg(&ob2[j]);
#pragma unroll 16
        for (int k = 0; k < 64; k++) v = fmaf(sbuf[gg * 64 + k], __ldg(&ow2[k * 64 + j]), v);
        sa[item] = fmaxf(v, 0.f);
    }
    __syncthreads();
#pragma unroll
    for (int it = 0; it < 4; it++) {
        int item = tid + it * 256;
        int gg = item >> 6, j = item & 63;
        float v = __ldg(&ob3[j]);
#pragma unroll 16
        for (int k = 0; k < 64; k++) v = fmaf(sa[gg * 64 + k], __ldg(&ow3[k * 64 + j]), v);
        sbuf[item] = fmaxf(v, 0.f);
    }
    __syncthreads();
    if (tid < NG * DOUT) {
        int gg = tid / DOUT, j = tid % DOUT;
        float o = __ldg(&ob4[j]);
#pragma unroll 16
        for (int k = 0; k < 64; k++)
            o = fmaf(sbuf[gg * 64 + k], __ldg(&ow4[k * DOUT + j]), o);
        out[gg * DOUT + j] = o;
    }
}

// ---------------------------------------------------------------------------
extern "C" void kernel_launch(void* const* d_in, const int* in_sizes, int n_in,
                              void* d_out, int out_size) {
    const float* x     = (const float*)d_in[0];
    const int* ei      = (const int*)d_in[1];
    const float* ea    = (const float*)d_in[2];
    const int* batch   = (const int*)d_in[3];
    const float* ew1 = (const float*)d_in[4];
    const float* eb1 = (const float*)d_in[5];
    const float* ew2 = (const float*)d_in[6];
    const float* eb2 = (const float*)d_in[7];
    const float* nw1 = (const float*)d_in[8];
    const float* nb1 = (const float*)d_in[9];
    const float* nw2 = (const float*)d_in[10];
    const float* nb2 = (const float*)d_in[11];
    const float* ow1 = (const float*)d_in[12];
    const float* ob1 = (const float*)d_in[13];
    const float* ow2 = (const float*)d_in[14];
    const float* ob2 = (const float*)d_in[15];
    const float* ow3 = (const float*)d_in[16];
    const float* ob3 = (const float*)d_in[17];
    const float* ow4 = (const float*)d_in[18];
    const float* ob4 = (const float*)d_in[19];
    float* out = (float*)d_out;

    const int node_smem = (4160 + NODES_B * VPAD + 64 + 1024) * 4;   // 90624 B
    static int smem_set = 0;
    if (!smem_set) {
        cudaFuncSetAttribute(node_out_kernel,
                             cudaFuncAttributeMaxDynamicSharedMemorySize, node_smem);
        smem_set = 1;
    }

    edge_kernel<<<NE / 256, 256>>>(x, ei, ea, ew1, eb1);               // 1
    node_out_kernel<<<(NN + NODES_B - 1) / NODES_B, 256, node_smem>>>( // 2
        x, batch, ew2, eb2, nw1, nb1, nw2, nb2,
        ow1, ob1, ow2, ob2, ow3, ob3, ow4, ob4, out);
}